// round 14
// baseline (speedup 1.0000x reference)
#include <cuda_runtime.h>
#include <cuda_bf16.h>
#include <math_constants.h>

// MultiLocalCosineLinear, fused single kernel (R13):
//   warp per row, 3 CTAs/SM (~84 reg budget) so the entire 12-float4 weight
//   burst can be in flight at once (phase-2 MLP 12 vs 4 at the 63-reg cap).
//     1) first_out row load (25 lanes x float4, .cs)   [chain head]
//     2) all 6 x float4 loads (.cs)                    [off-chain MLP]
//     3) top-2 via sortable-int keys + __reduce_{max,min}_sync
//     4) prefetch all 12 weight float4, then fused FMA block
//   out (float32): [0,B) preds, [B,3B) logits row-major (B,2)

#define NROWS   65536
#define DDIM    768
#define NCLS    100
#define F4L     6                 // 768/4/32

__device__ __forceinline__ float warp_sum(float v) {
    #pragma unroll
    for (int o = 16; o; o >>= 1) v += __shfl_xor_sync(0xffffffffu, v, o);
    return v;
}
__device__ __forceinline__ float4 ldcs_f4(const float4* p) {
    float4 v;
    asm volatile("ld.global.cs.v4.f32 {%0,%1,%2,%3}, [%4];"
                 : "=f"(v.x), "=f"(v.y), "=f"(v.z), "=f"(v.w) : "l"(p));
    return v;
}
// order-preserving float -> signed int key (-inf maps below all finite)
__device__ __forceinline__ int fkey(float f) {
    int i = __float_as_int(f);
    return (i >= 0) ? i : (i ^ 0x7fffffff);
}

__global__ __launch_bounds__(256, 3)
void mlcl_fused(const float* __restrict__ x,
                const float* __restrict__ first_out,
                const float* __restrict__ weights,
                const float* __restrict__ sigma,
                float* __restrict__ out)
{
    const int row  = blockIdx.x * 8 + (threadIdx.x >> 5);
    const int lane = threadIdx.x & 31;
    if (row >= NROWS) return;

    // 1) first_out row: one float4 per lane (25 active lanes) — chain head
    float4 fv;
    if (lane < 25) {
        const float4* fo4 = (const float4*)(first_out + (size_t)row * NCLS);
        fv = ldcs_f4(fo4 + lane);
    } else {
        fv = make_float4(-CUDART_INF_F, -CUDART_INF_F, -CUDART_INF_F, -CUDART_INF_F);
    }

    // 2) x row -> registers (streaming); independent of the top-2 chain
    const float4* x4 = (const float4*)(x + (size_t)row * DDIM);
    float4 xf[F4L];
    #pragma unroll
    for (int j = 0; j < F4L; ++j) xf[j] = ldcs_f4(x4 + lane + 32 * j);

    // 3) top-2 (jax.lax.top_k semantics: ties -> lower index)
    const int k0 = fkey(fv.x), k1 = fkey(fv.y);
    const int k2 = fkey(fv.z), k3 = fkey(fv.w);
    const int c0 = 4 * lane;

    int bk1 = k0, bi1 = c0;
    int bk2 = 0x80000000, bi2 = 0x7fffffff;
    if (k1 > bk1) { bk2 = bk1; bi2 = bi1; bk1 = k1; bi1 = c0 + 1; }
    else if (k1 > bk2) { bk2 = k1; bi2 = c0 + 1; }
    if (k2 > bk1) { bk2 = bk1; bi2 = bi1; bk1 = k2; bi1 = c0 + 2; }
    else if (k2 > bk2) { bk2 = k2; bi2 = c0 + 2; }
    if (k3 > bk1) { bk2 = bk1; bi2 = bi1; bk1 = k3; bi1 = c0 + 3; }
    else if (k3 > bk2) { bk2 = k3; bi2 = c0 + 3; }

    const int K1 = __reduce_max_sync(0xffffffffu, bk1);
    const int I1 = __reduce_min_sync(0xffffffffu, (bk1 == K1) ? bi1 : 0x7fffffff);
    const bool won = (bi1 == I1);
    const int sk = won ? bk2 : bk1;
    const int si = won ? bi2 : bi1;
    const int K2 = __reduce_max_sync(0xffffffffu, sk);
    const int I2 = __reduce_min_sync(0xffffffffu, (sk == K2) ? si : 0x7fffffff);

    const int a = min(I1, I2);
    const int b = max(I1, I2);
    const int pair = b * (b - 1) / 2 + a;

    // 4) prefetch ALL 12 weight float4 (48 regs) so every load is in flight
    //    before the FMA block consumes them.
    const float4* w4 = (const float4*)(weights + (size_t)pair * 2 * DDIM);
    float4 w0[F4L], w1[F4L];
    #pragma unroll
    for (int j = 0; j < F4L; ++j) w0[j] = __ldg(w4 + lane + 32 * j);
    #pragma unroll
    for (int j = 0; j < F4L; ++j) w1[j] = __ldg(w4 + 192 + lane + 32 * j);

    float xss = 0.f, d0 = 0.f, s0 = 0.f, d1 = 0.f, s1 = 0.f;
    #pragma unroll
    for (int j = 0; j < F4L; ++j) {
        const float4 v = xf[j];
        const float4 p = w0[j];
        const float4 q = w1[j];
        xss = fmaf(v.x, v.x, fmaf(v.y, v.y, fmaf(v.z, v.z, fmaf(v.w, v.w, xss))));
        d0  = fmaf(p.x, v.x, fmaf(p.y, v.y, fmaf(p.z, v.z, fmaf(p.w, v.w, d0))));
        s0  = fmaf(p.x, p.x, fmaf(p.y, p.y, fmaf(p.z, p.z, fmaf(p.w, p.w, s0))));
        d1  = fmaf(q.x, v.x, fmaf(q.y, v.y, fmaf(q.z, v.z, fmaf(q.w, v.w, d1))));
        s1  = fmaf(q.x, q.x, fmaf(q.y, q.y, fmaf(q.z, q.z, fmaf(q.w, q.w, s1))));
    }

    xss = warp_sum(xss);
    d0  = warp_sum(d0);
    s0  = warp_sum(s0);
    d1  = warp_sum(d1);
    s1  = warp_sum(s1);

    if (lane == 0) {
        const float sg   = __ldg(sigma + pair);
        const float xinv = 1.0f / fmaxf(sqrtf(xss), 1e-12f);
        const float l0 = sg * d0 * xinv / fmaxf(sqrtf(s0), 1e-12f);
        const float l1 = sg * d1 * xinv / fmaxf(sqrtf(s1), 1e-12f);
        out[row] = (float)((l1 > l0) ? b : a);       // argmax, first on tie
        *(float2*)(out + (size_t)NROWS + 2 * (size_t)row) = make_float2(l0, l1);
    }
}

extern "C" void kernel_launch(void* const* d_in, const int* in_sizes, int n_in,
                              void* d_out, int out_size) {
    const float* x        = (const float*)d_in[0];
    const float* first_o  = (const float*)d_in[1];
    const float* weights  = (const float*)d_in[2];
    const float* sigma    = (const float*)d_in[3];
    float* out = (float*)d_out;

    mlcl_fused<<<NROWS / 8, 256>>>(x, first_o, weights, sigma, out);
}

// round 15
// speedup vs baseline: 1.0901x; 1.0901x over previous
#include <cuda_runtime.h>
#include <cuda_bf16.h>
#include <math_constants.h>

// MultiLocalCosineLinear, direct-bucket binned pipeline (R14):
//   K0: zero per-pair counters
//   K1: warp per 4 rows; redux top-2 -> pair,(a,b); rank=atomicAdd(cnt[pair]);
//       rank<CAP -> g_bucket[pair*CAP+rank]=row, else overflow bit in g_info.
//   K2: one block (128 thr) per pair: weights -> SMEM once, norms once,
//       warps stream bucket rows (x loads issued before the smem fill).
//   K3: ballot overflow sweep (normally zero work) for rank>=CAP rows.
//   out (float32): [0,B) preds, [B,3B) logits row-major (B,2)

#define NROWS   65536
#define DDIM    768
#define NCLS    100
#define NPAIRS  4950
#define F4L     6                 // 768/4/32
#define CAP     64                // bucket capacity per pair (avg count 13.2)

__device__ int g_cnt[NPAIRS];
__device__ int g_info[NROWS];                 // pair | a<<13 | b<<20 | ovf<<27
__device__ int g_bucket[NPAIRS * CAP];

__device__ __forceinline__ float warp_sum(float v) {
    #pragma unroll
    for (int o = 16; o; o >>= 1) v += __shfl_xor_sync(0xffffffffu, v, o);
    return v;
}
__device__ __forceinline__ float4 ldcs_f4(const float4* p) {
    float4 v;
    asm volatile("ld.global.cs.v4.f32 {%0,%1,%2,%3}, [%4];"
                 : "=f"(v.x), "=f"(v.y), "=f"(v.z), "=f"(v.w) : "l"(p));
    return v;
}
__device__ __forceinline__ int fkey(float f) {     // order-preserving key
    int i = __float_as_int(f);
    return (i >= 0) ? i : (i ^ 0x7fffffff);
}

// ---------------- K0 ----------------
__global__ void k_zero() {
    int i = blockIdx.x * blockDim.x + threadIdx.x;
    if (i < NPAIRS) g_cnt[i] = 0;
}

// ---------------- K1: redux top-2, 4 rows/warp, direct bucket append ----------------
__global__ __launch_bounds__(256, 4)
void k_top2(const float* __restrict__ first_out) {
    const int warp = blockIdx.x * 8 + (threadIdx.x >> 5);
    const int lane = threadIdx.x & 31;
    const int r0   = warp * 4;
    if (r0 >= NROWS) return;

    float4 fv[4];
    #pragma unroll
    for (int t = 0; t < 4; ++t) {
        if (lane < 25) {
            const float4* fo4 = (const float4*)(first_out + (size_t)(r0 + t) * NCLS);
            fv[t] = ldcs_f4(fo4 + lane);
        } else {
            fv[t] = make_float4(-CUDART_INF_F, -CUDART_INF_F, -CUDART_INF_F, -CUDART_INF_F);
        }
    }

    #pragma unroll
    for (int t = 0; t < 4; ++t) {
        const int k0 = fkey(fv[t].x), k1 = fkey(fv[t].y);
        const int k2 = fkey(fv[t].z), k3 = fkey(fv[t].w);
        const int c0 = 4 * lane;

        int bk1 = k0, bi1 = c0;
        int bk2 = 0x80000000, bi2 = 0x7fffffff;
        if (k1 > bk1) { bk2 = bk1; bi2 = bi1; bk1 = k1; bi1 = c0 + 1; }
        else if (k1 > bk2) { bk2 = k1; bi2 = c0 + 1; }
        if (k2 > bk1) { bk2 = bk1; bi2 = bi1; bk1 = k2; bi1 = c0 + 2; }
        else if (k2 > bk2) { bk2 = k2; bi2 = c0 + 2; }
        if (k3 > bk1) { bk2 = bk1; bi2 = bi1; bk1 = k3; bi1 = c0 + 3; }
        else if (k3 > bk2) { bk2 = k3; bi2 = c0 + 3; }

        const int K1 = __reduce_max_sync(0xffffffffu, bk1);
        const int I1 = __reduce_min_sync(0xffffffffu, (bk1 == K1) ? bi1 : 0x7fffffff);
        const bool won = (bi1 == I1);
        const int sk = won ? bk2 : bk1;
        const int si = won ? bi2 : bi1;
        const int K2 = __reduce_max_sync(0xffffffffu, sk);
        const int I2 = __reduce_min_sync(0xffffffffu, (sk == K2) ? si : 0x7fffffff);

        if (lane == 0) {
            const int a = min(I1, I2);
            const int b = max(I1, I2);
            const int pair = b * (b - 1) / 2 + a;
            const int rank = atomicAdd(&g_cnt[pair], 1);
            int info = pair | (a << 13) | (b << 20);
            if (rank < CAP) g_bucket[pair * CAP + rank] = r0 + t;
            else            info |= (1 << 27);
            g_info[r0 + t] = info;
        }
    }
}

// ---------------- K2: one block per pair, weights in SMEM ----------------
__global__ __launch_bounds__(128, 8)
void k_compute(const float* __restrict__ x,
               const float* __restrict__ weights,
               const float* __restrict__ sigma,
               float* __restrict__ out)
{
    const int pair = blockIdx.x;
    const int cnt  = min(g_cnt[pair], CAP);
    if (cnt == 0) return;

    __shared__ float4 sW[2 * DDIM / 4];     // 384 float4 = 6 KB
    __shared__ float  s_scale[2];

    const int tid  = threadIdx.x;
    const int wid  = tid >> 5;
    const int lane = tid & 31;

    // first row per warp: fetch id and issue x loads BEFORE the smem fill
    int myrow = -1;
    float4 xf[F4L];
    if (wid < cnt) {
        myrow = g_bucket[pair * CAP + wid];
        const float4* x4 = (const float4*)(x + (size_t)myrow * DDIM);
        #pragma unroll
        for (int j = 0; j < F4L; ++j) xf[j] = ldcs_f4(x4 + lane + 32 * j);
    }

    // cooperative weight fill (3 float4 per thread)
    const float4* w4 = (const float4*)(weights + (size_t)pair * 2 * DDIM);
    #pragma unroll
    for (int i = tid; i < 2 * DDIM / 4; i += 128) sW[i] = __ldg(w4 + i);
    __syncthreads();

    // norms once (warps 0,1)
    if (wid < 2) {
        float wss = 0.f;
        const float4* wr = sW + wid * (DDIM / 4);
        #pragma unroll
        for (int j = 0; j < F4L; ++j) {
            float4 w = wr[lane + 32 * j];
            wss = fmaf(w.x, w.x, fmaf(w.y, w.y, fmaf(w.z, w.z, fmaf(w.w, w.w, wss))));
        }
        wss = warp_sum(wss);
        if (lane == 0)
            s_scale[wid] = __ldg(sigma + pair) / fmaxf(sqrtf(wss), 1e-12f);
    }
    __syncthreads();
    const float sc0 = s_scale[0];
    const float sc1 = s_scale[1];

    for (int r = wid; r < cnt; r += 4) {
        if (r != wid) {
            myrow = g_bucket[pair * CAP + r];
            const float4* x4 = (const float4*)(x + (size_t)myrow * DDIM);
            #pragma unroll
            for (int j = 0; j < F4L; ++j) xf[j] = ldcs_f4(x4 + lane + 32 * j);
        }
        float xss = 0.f, d0 = 0.f, d1 = 0.f;
        #pragma unroll
        for (int j = 0; j < F4L; ++j) {
            const float4 v = xf[j];
            const float4 p = sW[lane + 32 * j];
            const float4 q = sW[DDIM / 4 + lane + 32 * j];
            xss = fmaf(v.x, v.x, fmaf(v.y, v.y, fmaf(v.z, v.z, fmaf(v.w, v.w, xss))));
            d0  = fmaf(p.x, v.x, fmaf(p.y, v.y, fmaf(p.z, v.z, fmaf(p.w, v.w, d0))));
            d1  = fmaf(q.x, v.x, fmaf(q.y, v.y, fmaf(q.z, v.z, fmaf(q.w, v.w, d1))));
        }
        xss = warp_sum(xss);
        d0  = warp_sum(d0);
        d1  = warp_sum(d1);

        if (lane == 0) {
            const float xinv = 1.0f / fmaxf(sqrtf(xss), 1e-12f);
            const float l0 = sc0 * d0 * xinv;
            const float l1 = sc1 * d1 * xinv;
            const int info = g_info[myrow];
            const int a = (info >> 13) & 127;
            const int b = (info >> 20) & 127;
            out[myrow] = (float)((l1 > l0) ? b : a);   // argmax, first on tie
            *(float2*)(out + (size_t)NROWS + 2 * (size_t)myrow) = make_float2(l0, l1);
        }
    }
}

// ---------------- K3: overflow sweep (normally zero work) ----------------
__global__ __launch_bounds__(256, 4)
void k_overflow(const float* __restrict__ x,
                const float* __restrict__ weights,
                const float* __restrict__ sigma,
                float* __restrict__ out)
{
    const int wid  = threadIdx.x >> 5;
    const int lane = threadIdx.x & 31;
    const int base = (blockIdx.x * 8 + wid) * 32;
    if (base >= NROWS) return;

    const int info = g_info[base + lane];
    unsigned m = __ballot_sync(0xffffffffu, (info >> 27) & 1);
    while (m) {
        const int idx = __ffs(m) - 1; m &= m - 1;
        const int rinfo = __shfl_sync(0xffffffffu, info, idx);
        const int row   = base + idx;
        const int pair  = rinfo & 8191;

        const float4* x4 = (const float4*)(x + (size_t)row * DDIM);
        const float4* w4 = (const float4*)(weights + (size_t)pair * 2 * DDIM);
        float4 xf[F4L];
        #pragma unroll
        for (int j = 0; j < F4L; ++j) xf[j] = ldcs_f4(x4 + lane + 32 * j);

        // mirror K2's math exactly (norms first, same fma order)
        float wss0 = 0.f, wss1 = 0.f;
        float xss = 0.f, d0 = 0.f, d1 = 0.f;
        #pragma unroll
        for (int j = 0; j < F4L; ++j) {
            const float4 p = __ldg(w4 + lane + 32 * j);
            const float4 q = __ldg(w4 + 192 + lane + 32 * j);
            const float4 v = xf[j];
            wss0 = fmaf(p.x, p.x, fmaf(p.y, p.y, fmaf(p.z, p.z, fmaf(p.w, p.w, wss0))));
            wss1 = fmaf(q.x, q.x, fmaf(q.y, q.y, fmaf(q.z, q.z, fmaf(q.w, q.w, wss1))));
            xss  = fmaf(v.x, v.x, fmaf(v.y, v.y, fmaf(v.z, v.z, fmaf(v.w, v.w, xss))));
            d0   = fmaf(p.x, v.x, fmaf(p.y, v.y, fmaf(p.z, v.z, fmaf(p.w, v.w, d0))));
            d1   = fmaf(q.x, v.x, fmaf(q.y, v.y, fmaf(q.z, v.z, fmaf(q.w, v.w, d1))));
        }
        wss0 = warp_sum(wss0);
        wss1 = warp_sum(wss1);
        xss  = warp_sum(xss);
        d0   = warp_sum(d0);
        d1   = warp_sum(d1);

        if (lane == 0) {
            const float sg  = __ldg(sigma + pair);
            const float sc0 = sg / fmaxf(sqrtf(wss0), 1e-12f);
            const float sc1 = sg / fmaxf(sqrtf(wss1), 1e-12f);
            const float xinv = 1.0f / fmaxf(sqrtf(xss), 1e-12f);
            const float l0 = sc0 * d0 * xinv;
            const float l1 = sc1 * d1 * xinv;
            const int a = (rinfo >> 13) & 127;
            const int b = (rinfo >> 20) & 127;
            out[row] = (float)((l1 > l0) ? b : a);
            *(float2*)(out + (size_t)NROWS + 2 * (size_t)row) = make_float2(l0, l1);
        }
    }
}

extern "C" void kernel_launch(void* const* d_in, const int* in_sizes, int n_in,
                              void* d_out, int out_size) {
    const float* x        = (const float*)d_in[0];
    const float* first_o  = (const float*)d_in[1];
    const float* weights  = (const float*)d_in[2];
    const float* sigma    = (const float*)d_in[3];
    float* out = (float*)d_out;

    k_zero<<<(NPAIRS + 255) / 256, 256>>>();
    k_top2<<<NROWS / 32, 256>>>(first_o);
    k_compute<<<NPAIRS, 128>>>(x, weights, sigma, out);
    k_overflow<<<NROWS / 256, 256>>>(x, weights, sigma, out);
}

// round 16
// speedup vs baseline: 1.1301x; 1.0367x over previous
#include <cuda_runtime.h>
#include <cuda_bf16.h>
#include <math_constants.h>

// MultiLocalCosineLinear, direct-bucket binned pipeline (R15, 2 launches):
//   K1: warp per 4 rows; redux top-2 -> pair,(a,b); rank=atomicAdd(cnt[pair]);
//       rank<CAP -> g_bucket[pair*CAP+rank]=row, else overflow bit in g_info.
//   K2: one block (128 thr) per pair: weights -> SMEM once, norms once,
//       warps stream bucket rows; tail: sweep a 14-row g_info slice for
//       overflow rows (normally none) and reset g_cnt[pair] for next replay.
//   out (float32): [0,B) preds, [B,3B) logits row-major (B,2)

#define NROWS   65536
#define DDIM    768
#define NCLS    100
#define NPAIRS  4950
#define F4L     6                 // 768/4/32
#define CAP     64                // bucket capacity per pair (avg count 13.2)
#define SLICE   14                // ceil(NROWS / NPAIRS) rows swept per block

__device__ int g_cnt[NPAIRS];                 // zero-init; reset by k_compute
__device__ int g_info[NROWS];                 // pair | a<<13 | b<<20 | ovf<<27
__device__ int g_bucket[NPAIRS * CAP];

__device__ __forceinline__ float warp_sum(float v) {
    #pragma unroll
    for (int o = 16; o; o >>= 1) v += __shfl_xor_sync(0xffffffffu, v, o);
    return v;
}
__device__ __forceinline__ float4 ldcs_f4(const float4* p) {
    float4 v;
    asm volatile("ld.global.cs.v4.f32 {%0,%1,%2,%3}, [%4];"
                 : "=f"(v.x), "=f"(v.y), "=f"(v.z), "=f"(v.w) : "l"(p));
    return v;
}
__device__ __forceinline__ int fkey(float f) {     // order-preserving key
    int i = __float_as_int(f);
    return (i >= 0) ? i : (i ^ 0x7fffffff);
}

// ---------------- K1: redux top-2, 4 rows/warp, direct bucket append ----------------
__global__ __launch_bounds__(256, 4)
void k_top2(const float* __restrict__ first_out) {
    const int warp = blockIdx.x * 8 + (threadIdx.x >> 5);
    const int lane = threadIdx.x & 31;
    const int r0   = warp * 4;
    if (r0 >= NROWS) return;

    float4 fv[4];
    #pragma unroll
    for (int t = 0; t < 4; ++t) {
        if (lane < 25) {
            const float4* fo4 = (const float4*)(first_out + (size_t)(r0 + t) * NCLS);
            fv[t] = ldcs_f4(fo4 + lane);
        } else {
            fv[t] = make_float4(-CUDART_INF_F, -CUDART_INF_F, -CUDART_INF_F, -CUDART_INF_F);
        }
    }

    #pragma unroll
    for (int t = 0; t < 4; ++t) {
        const int k0 = fkey(fv[t].x), k1 = fkey(fv[t].y);
        const int k2 = fkey(fv[t].z), k3 = fkey(fv[t].w);
        const int c0 = 4 * lane;

        int bk1 = k0, bi1 = c0;
        int bk2 = 0x80000000, bi2 = 0x7fffffff;
        if (k1 > bk1) { bk2 = bk1; bi2 = bi1; bk1 = k1; bi1 = c0 + 1; }
        else if (k1 > bk2) { bk2 = k1; bi2 = c0 + 1; }
        if (k2 > bk1) { bk2 = bk1; bi2 = bi1; bk1 = k2; bi1 = c0 + 2; }
        else if (k2 > bk2) { bk2 = k2; bi2 = c0 + 2; }
        if (k3 > bk1) { bk2 = bk1; bi2 = bi1; bk1 = k3; bi1 = c0 + 3; }
        else if (k3 > bk2) { bk2 = k3; bi2 = c0 + 3; }

        const int K1 = __reduce_max_sync(0xffffffffu, bk1);
        const int I1 = __reduce_min_sync(0xffffffffu, (bk1 == K1) ? bi1 : 0x7fffffff);
        const bool won = (bi1 == I1);
        const int sk = won ? bk2 : bk1;
        const int si = won ? bi2 : bi1;
        const int K2 = __reduce_max_sync(0xffffffffu, sk);
        const int I2 = __reduce_min_sync(0xffffffffu, (sk == K2) ? si : 0x7fffffff);

        if (lane == 0) {
            const int a = min(I1, I2);
            const int b = max(I1, I2);
            const int pair = b * (b - 1) / 2 + a;
            const int rank = atomicAdd(&g_cnt[pair], 1);
            int info = pair | (a << 13) | (b << 20);
            if (rank < CAP) g_bucket[pair * CAP + rank] = r0 + t;
            else            info |= (1 << 27);
            g_info[r0 + t] = info;
        }
    }
}

// ---------------- K2: one block per pair, weights in SMEM + overflow tail ----------------
__global__ __launch_bounds__(128, 8)
void k_compute(const float* __restrict__ x,
               const float* __restrict__ weights,
               const float* __restrict__ sigma,
               float* __restrict__ out)
{
    const int pair = blockIdx.x;
    const int cnt  = min(g_cnt[pair], CAP);

    __shared__ float4 sW[2 * DDIM / 4];     // 6 KB
    __shared__ float  s_scale[2];
    __shared__ int    s_ovf[SLICE];
    __shared__ int    s_novf;

    const int tid  = threadIdx.x;
    const int wid  = tid >> 5;
    const int lane = tid & 31;

    if (cnt > 0) {
        // first row per warp: fetch id and issue x loads BEFORE the smem fill
        int myrow = -1;
        float4 xf[F4L];
        if (wid < cnt) {
            myrow = g_bucket[pair * CAP + wid];
            const float4* x4 = (const float4*)(x + (size_t)myrow * DDIM);
            #pragma unroll
            for (int j = 0; j < F4L; ++j) xf[j] = ldcs_f4(x4 + lane + 32 * j);
        }

        // cooperative weight fill (3 float4 per thread)
        const float4* w4 = (const float4*)(weights + (size_t)pair * 2 * DDIM);
        #pragma unroll
        for (int i = tid; i < 2 * DDIM / 4; i += 128) sW[i] = __ldg(w4 + i);
        __syncthreads();

        // norms once (warps 0,1)
        if (wid < 2) {
            float wss = 0.f;
            const float4* wr = sW + wid * (DDIM / 4);
            #pragma unroll
            for (int j = 0; j < F4L; ++j) {
                float4 w = wr[lane + 32 * j];
                wss = fmaf(w.x, w.x, fmaf(w.y, w.y, fmaf(w.z, w.z, fmaf(w.w, w.w, wss))));
            }
            wss = warp_sum(wss);
            if (lane == 0)
                s_scale[wid] = __ldg(sigma + pair) / fmaxf(sqrtf(wss), 1e-12f);
        }
        __syncthreads();
        const float sc0 = s_scale[0];
        const float sc1 = s_scale[1];

        for (int r = wid; r < cnt; r += 4) {
            if (r != wid) {
                myrow = g_bucket[pair * CAP + r];
                const float4* x4 = (const float4*)(x + (size_t)myrow * DDIM);
                #pragma unroll
                for (int j = 0; j < F4L; ++j) xf[j] = ldcs_f4(x4 + lane + 32 * j);
            }
            float xss = 0.f, d0 = 0.f, d1 = 0.f;
            #pragma unroll
            for (int j = 0; j < F4L; ++j) {
                const float4 v = xf[j];
                const float4 p = sW[lane + 32 * j];
                const float4 q = sW[DDIM / 4 + lane + 32 * j];
                xss = fmaf(v.x, v.x, fmaf(v.y, v.y, fmaf(v.z, v.z, fmaf(v.w, v.w, xss))));
                d0  = fmaf(p.x, v.x, fmaf(p.y, v.y, fmaf(p.z, v.z, fmaf(p.w, v.w, d0))));
                d1  = fmaf(q.x, v.x, fmaf(q.y, v.y, fmaf(q.z, v.z, fmaf(q.w, v.w, d1))));
            }
            xss = warp_sum(xss);
            d0  = warp_sum(d0);
            d1  = warp_sum(d1);

            if (lane == 0) {
                const float xinv = 1.0f / fmaxf(sqrtf(xss), 1e-12f);
                const float l0 = sc0 * d0 * xinv;
                const float l1 = sc1 * d1 * xinv;
                const int info = g_info[myrow];
                const int a = (info >> 13) & 127;
                const int b = (info >> 20) & 127;
                out[myrow] = (float)((l1 > l0) ? b : a);   // argmax, first on tie
                *(float2*)(out + (size_t)NROWS + 2 * (size_t)myrow) = make_float2(l0, l1);
            }
        }
    }

    // ---- overflow sweep over this block's 14-row slice (normally empty) ----
    if (tid == 0) s_novf = 0;
    __syncthreads();
    if (tid < SLICE) {
        const int r = pair * SLICE + tid;
        if (r < NROWS) {
            const int inf = g_info[r];
            if ((inf >> 27) & 1) {
                const int p = atomicAdd(&s_novf, 1);
                s_ovf[p] = r;
            }
        }
    }
    __syncthreads();

    const int novf = s_novf;
    if (wid == 0) {                      // warp 0 handles rare overflow rows
        for (int i = 0; i < novf; ++i) {
            const int row   = s_ovf[i];
            const int rinfo = g_info[row];
            const int rp    = rinfo & 8191;

            const float4* x4 = (const float4*)(x + (size_t)row * DDIM);
            const float4* w4 = (const float4*)(weights + (size_t)rp * 2 * DDIM);
            float wss0 = 0.f, wss1 = 0.f, xss = 0.f, d0 = 0.f, d1 = 0.f;
            #pragma unroll
            for (int j = 0; j < F4L; ++j) {
                const float4 v = ldcs_f4(x4 + lane + 32 * j);
                const float4 p = __ldg(w4 + lane + 32 * j);
                const float4 q = __ldg(w4 + 192 + lane + 32 * j);
                wss0 = fmaf(p.x, p.x, fmaf(p.y, p.y, fmaf(p.z, p.z, fmaf(p.w, p.w, wss0))));
                wss1 = fmaf(q.x, q.x, fmaf(q.y, q.y, fmaf(q.z, q.z, fmaf(q.w, q.w, wss1))));
                xss  = fmaf(v.x, v.x, fmaf(v.y, v.y, fmaf(v.z, v.z, fmaf(v.w, v.w, xss))));
                d0   = fmaf(p.x, v.x, fmaf(p.y, v.y, fmaf(p.z, v.z, fmaf(p.w, v.w, d0))));
                d1   = fmaf(q.x, v.x, fmaf(q.y, v.y, fmaf(q.z, v.z, fmaf(q.w, v.w, d1))));
            }
            wss0 = warp_sum(wss0);
            wss1 = warp_sum(wss1);
            xss  = warp_sum(xss);
            d0   = warp_sum(d0);
            d1   = warp_sum(d1);

            if (lane == 0) {
                const float sg  = __ldg(sigma + rp);
                const float sc0 = sg / fmaxf(sqrtf(wss0), 1e-12f);
                const float sc1 = sg / fmaxf(sqrtf(wss1), 1e-12f);
                const float xinv = 1.0f / fmaxf(sqrtf(xss), 1e-12f);
                const float l0 = sc0 * d0 * xinv;
                const float l1 = sc1 * d1 * xinv;
                const int a = (rinfo >> 13) & 127;
                const int b = (rinfo >> 20) & 127;
                out[row] = (float)((l1 > l0) ? b : a);
                *(float2*)(out + (size_t)NROWS + 2 * (size_t)row) = make_float2(l0, l1);
            }
        }
    }

    // reset counter so the next graph replay starts clean
    if (tid == 0) g_cnt[pair] = 0;
}

extern "C" void kernel_launch(void* const* d_in, const int* in_sizes, int n_in,
                              void* d_out, int out_size) {
    const float* x        = (const float*)d_in[0];
    const float* first_o  = (const float*)d_in[1];
    const float* weights  = (const float*)d_in[2];
    const float* sigma    = (const float*)d_in[3];
    float* out = (float*)d_out;

    k_top2<<<NROWS / 32, 256>>>(first_o);
    k_compute<<<NPAIRS, 128>>>(x, weights, sigma, out);
}

// round 17
// speedup vs baseline: 1.1642x; 1.0301x over previous
#include <cuda_runtime.h>
#include <cuda_bf16.h>
#include <math_constants.h>

// MultiLocalCosineLinear, direct-bucket binned pipeline (R16):
//   K1: warp per 4 rows; redux top-2 -> pair,(a,b); rank=atomicAdd(cnt[pair]);
//       rank<CAP -> g_bucket[pair*CAP+rank]=row, else overflow bit in g_info.
//   K2: one block (128 thr) per pair: weights -> SMEM once, norms once,
//       warps stream bucket rows SOFTWARE-PIPELINED: next row's x loads are
//       issued into the (dead) xf registers before the current row's
//       warp_sums, so reductions overlap memory latency.
//       Tail: overflow sweep of a 14-row g_info slice + g_cnt reset.
//   out (float32): [0,B) preds, [B,3B) logits row-major (B,2)

#define NROWS   65536
#define DDIM    768
#define NCLS    100
#define NPAIRS  4950
#define F4L     6                 // 768/4/32
#define CAP     64                // bucket capacity per pair (avg count 13.2)
#define SLICE   14                // ceil(NROWS / NPAIRS) rows swept per block

__device__ int g_cnt[NPAIRS];                 // zero-init; reset by k_compute
__device__ int g_info[NROWS];                 // pair | a<<13 | b<<20 | ovf<<27
__device__ int g_bucket[NPAIRS * CAP];

__device__ __forceinline__ float warp_sum(float v) {
    #pragma unroll
    for (int o = 16; o; o >>= 1) v += __shfl_xor_sync(0xffffffffu, v, o);
    return v;
}
__device__ __forceinline__ float4 ldcs_f4(const float4* p) {
    float4 v;
    asm volatile("ld.global.cs.v4.f32 {%0,%1,%2,%3}, [%4];"
                 : "=f"(v.x), "=f"(v.y), "=f"(v.z), "=f"(v.w) : "l"(p));
    return v;
}
__device__ __forceinline__ int fkey(float f) {     // order-preserving key
    int i = __float_as_int(f);
    return (i >= 0) ? i : (i ^ 0x7fffffff);
}

// ---------------- K1: redux top-2, 4 rows/warp, direct bucket append ----------------
__global__ __launch_bounds__(256, 4)
void k_top2(const float* __restrict__ first_out) {
    const int warp = blockIdx.x * 8 + (threadIdx.x >> 5);
    const int lane = threadIdx.x & 31;
    const int r0   = warp * 4;
    if (r0 >= NROWS) return;

    float4 fv[4];
    #pragma unroll
    for (int t = 0; t < 4; ++t) {
        if (lane < 25) {
            const float4* fo4 = (const float4*)(first_out + (size_t)(r0 + t) * NCLS);
            fv[t] = ldcs_f4(fo4 + lane);
        } else {
            fv[t] = make_float4(-CUDART_INF_F, -CUDART_INF_F, -CUDART_INF_F, -CUDART_INF_F);
        }
    }

    #pragma unroll
    for (int t = 0; t < 4; ++t) {
        const int k0 = fkey(fv[t].x), k1 = fkey(fv[t].y);
        const int k2 = fkey(fv[t].z), k3 = fkey(fv[t].w);
        const int c0 = 4 * lane;

        int bk1 = k0, bi1 = c0;
        int bk2 = 0x80000000, bi2 = 0x7fffffff;
        if (k1 > bk1) { bk2 = bk1; bi2 = bi1; bk1 = k1; bi1 = c0 + 1; }
        else if (k1 > bk2) { bk2 = k1; bi2 = c0 + 1; }
        if (k2 > bk1) { bk2 = bk1; bi2 = bi1; bk1 = k2; bi1 = c0 + 2; }
        else if (k2 > bk2) { bk2 = k2; bi2 = c0 + 2; }
        if (k3 > bk1) { bk2 = bk1; bi2 = bi1; bk1 = k3; bi1 = c0 + 3; }
        else if (k3 > bk2) { bk2 = k3; bi2 = c0 + 3; }

        const int K1 = __reduce_max_sync(0xffffffffu, bk1);
        const int I1 = __reduce_min_sync(0xffffffffu, (bk1 == K1) ? bi1 : 0x7fffffff);
        const bool won = (bi1 == I1);
        const int sk = won ? bk2 : bk1;
        const int si = won ? bi2 : bi1;
        const int K2 = __reduce_max_sync(0xffffffffu, sk);
        const int I2 = __reduce_min_sync(0xffffffffu, (sk == K2) ? si : 0x7fffffff);

        if (lane == 0) {
            const int a = min(I1, I2);
            const int b = max(I1, I2);
            const int pair = b * (b - 1) / 2 + a;
            const int rank = atomicAdd(&g_cnt[pair], 1);
            int info = pair | (a << 13) | (b << 20);
            if (rank < CAP) g_bucket[pair * CAP + rank] = r0 + t;
            else            info |= (1 << 27);
            g_info[r0 + t] = info;
        }
    }
}

// ---------------- K2: block per pair, SMEM weights, pipelined row loop ----------------
__global__ __launch_bounds__(128, 8)
void k_compute(const float* __restrict__ x,
               const float* __restrict__ weights,
               const float* __restrict__ sigma,
               float* __restrict__ out)
{
    const int pair = blockIdx.x;
    const int cnt  = min(g_cnt[pair], CAP);

    __shared__ float4 sW[2 * DDIM / 4];     // 6 KB
    __shared__ float  s_scale[2];
    __shared__ int    s_ovf[SLICE];
    __shared__ int    s_novf;

    const int tid  = threadIdx.x;
    const int wid  = tid >> 5;
    const int lane = tid & 31;

    if (cnt > 0) {
        // first row per warp: fetch id and issue x loads BEFORE the smem fill
        int r = wid;
        int myrow = (r < cnt) ? g_bucket[pair * CAP + r] : -1;
        float4 xf[F4L];
        if (myrow >= 0) {
            const float4* x4 = (const float4*)(x + (size_t)myrow * DDIM);
            #pragma unroll
            for (int j = 0; j < F4L; ++j) xf[j] = ldcs_f4(x4 + lane + 32 * j);
        }

        // cooperative weight fill (3 float4 per thread)
        const float4* w4 = (const float4*)(weights + (size_t)pair * 2 * DDIM);
        #pragma unroll
        for (int i = tid; i < 2 * DDIM / 4; i += 128) sW[i] = __ldg(w4 + i);
        __syncthreads();

        // norms once (warps 0,1)
        if (wid < 2) {
            float wss = 0.f;
            const float4* wr = sW + wid * (DDIM / 4);
            #pragma unroll
            for (int j = 0; j < F4L; ++j) {
                float4 w = wr[lane + 32 * j];
                wss = fmaf(w.x, w.x, fmaf(w.y, w.y, fmaf(w.z, w.z, fmaf(w.w, w.w, wss))));
            }
            wss = warp_sum(wss);
            if (lane == 0)
                s_scale[wid] = __ldg(sigma + pair) / fmaxf(sqrtf(wss), 1e-12f);
        }
        __syncthreads();
        const float sc0 = s_scale[0];
        const float sc1 = s_scale[1];

        while (myrow >= 0) {
            // consume xf
            float xss = 0.f, d0 = 0.f, d1 = 0.f;
            #pragma unroll
            for (int j = 0; j < F4L; ++j) {
                const float4 v = xf[j];
                const float4 p = sW[lane + 32 * j];
                const float4 q = sW[DDIM / 4 + lane + 32 * j];
                xss = fmaf(v.x, v.x, fmaf(v.y, v.y, fmaf(v.z, v.z, fmaf(v.w, v.w, xss))));
                d0  = fmaf(p.x, v.x, fmaf(p.y, v.y, fmaf(p.z, v.z, fmaf(p.w, v.w, d0))));
                d1  = fmaf(q.x, v.x, fmaf(q.y, v.y, fmaf(q.z, v.z, fmaf(q.w, v.w, d1))));
            }

            // PIPELINE: xf is now dead -> issue next row's loads into it
            // before the reduction chains, so shuffles overlap memory latency.
            const int nr = r + 4;
            const int nextrow = (nr < cnt) ? g_bucket[pair * CAP + nr] : -1;
            if (nextrow >= 0) {
                const float4* x4 = (const float4*)(x + (size_t)nextrow * DDIM);
                #pragma unroll
                for (int j = 0; j < F4L; ++j) xf[j] = ldcs_f4(x4 + lane + 32 * j);
            }

            xss = warp_sum(xss);
            d0  = warp_sum(d0);
            d1  = warp_sum(d1);

            if (lane == 0) {
                const float xinv = 1.0f / fmaxf(sqrtf(xss), 1e-12f);
                const float l0 = sc0 * d0 * xinv;
                const float l1 = sc1 * d1 * xinv;
                const int info = g_info[myrow];
                const int a = (info >> 13) & 127;
                const int b = (info >> 20) & 127;
                out[myrow] = (float)((l1 > l0) ? b : a);   // argmax, first on tie
                *(float2*)(out + (size_t)NROWS + 2 * (size_t)myrow) = make_float2(l0, l1);
            }

            myrow = nextrow;
            r = nr;
        }
    }

    // ---- overflow sweep over this block's 14-row slice (normally empty) ----
    if (tid == 0) s_novf = 0;
    __syncthreads();
    if (tid < SLICE) {
        const int rr = pair * SLICE + tid;
        if (rr < NROWS) {
            const int inf = g_info[rr];
            if ((inf >> 27) & 1) {
                const int p = atomicAdd(&s_novf, 1);
                s_ovf[p] = rr;
            }
        }
    }
    __syncthreads();

    const int novf = s_novf;
    if (wid == 0) {                      // warp 0 handles rare overflow rows
        for (int i = 0; i < novf; ++i) {
            const int row   = s_ovf[i];
            const int rinfo = g_info[row];
            const int rp    = rinfo & 8191;

            const float4* x4 = (const float4*)(x + (size_t)row * DDIM);
            const float4* wv = (const float4*)(weights + (size_t)rp * 2 * DDIM);
            float wss0 = 0.f, wss1 = 0.f, xss = 0.f, d0 = 0.f, d1 = 0.f;
            #pragma unroll
            for (int j = 0; j < F4L; ++j) {
                const float4 v = ldcs_f4(x4 + lane + 32 * j);
                const float4 p = __ldg(wv + lane + 32 * j);
                const float4 q = __ldg(wv + 192 + lane + 32 * j);
                wss0 = fmaf(p.x, p.x, fmaf(p.y, p.y, fmaf(p.z, p.z, fmaf(p.w, p.w, wss0))));
                wss1 = fmaf(q.x, q.x, fmaf(q.y, q.y, fmaf(q.z, q.z, fmaf(q.w, q.w, wss1))));
                xss  = fmaf(v.x, v.x, fmaf(v.y, v.y, fmaf(v.z, v.z, fmaf(v.w, v.w, xss))));
                d0   = fmaf(p.x, v.x, fmaf(p.y, v.y, fmaf(p.z, v.z, fmaf(p.w, v.w, d0))));
                d1   = fmaf(q.x, v.x, fmaf(q.y, v.y, fmaf(q.z, v.z, fmaf(q.w, v.w, d1))));
            }
            wss0 = warp_sum(wss0);
            wss1 = warp_sum(wss1);
            xss  = warp_sum(xss);
            d0   = warp_sum(d0);
            d1   = warp_sum(d1);

            if (lane == 0) {
                const float sg  = __ldg(sigma + rp);
                const float sc0 = sg / fmaxf(sqrtf(wss0), 1e-12f);
                const float sc1 = sg / fmaxf(sqrtf(wss1), 1e-12f);
                const float xinv = 1.0f / fmaxf(sqrtf(xss), 1e-12f);
                const float l0 = sc0 * d0 * xinv;
                const float l1 = sc1 * d1 * xinv;
                const int a = (rinfo >> 13) & 127;
                const int b = (rinfo >> 20) & 127;
                out[row] = (float)((l1 > l0) ? b : a);
                *(float2*)(out + (size_t)NROWS + 2 * (size_t)row) = make_float2(l0, l1);
            }
        }
    }

    // reset counter so the next graph replay starts clean
    if (tid == 0) g_cnt[pair] = 0;
}

extern "C" void kernel_launch(void* const* d_in, const int* in_sizes, int n_in,
                              void* d_out, int out_size) {
    const float* x        = (const float*)d_in[0];
    const float* first_o  = (const float*)d_in[1];
    const float* weights  = (const float*)d_in[2];
    const float* sigma    = (const float*)d_in[3];
    float* out = (float*)d_out;

    k_top2<<<NROWS / 32, 256>>>(first_o);
    k_compute<<<NPAIRS, 128>>>(x, weights, sigma, out);
}